// round 13
// baseline (speedup 1.0000x reference)
#include <cuda_runtime.h>
#include <cuda_bf16.h>
#include <cstdint>

// ============================================================================
// ReuploadingQuantumLayer: 10-qubit statevector sim, 4 layers, B=16384.
// TWO warps per batch element (64 lanes): 16 amps/lane = 8 packed f32x2 RE +
// 8 packed IM regs. Physical index bits: [0..2]=pack, [3]=slot, [4..8]=lane,
// [9]=warp. Cross-warp gates (8 of 30) exchange state via shared memory with
// named 64-thread barriers; cross-lane gates (16) use shfl; 6 gates are
// register-local. CNOT rings tracked as compile-time GF(2) basis transform.
// Layer 0 exploits |0..0>: direct product-state construction.
// All arithmetic via Blackwell packed fma.rn.f32x2.
// ============================================================================

#define FULLM 0xFFFFFFFFu
typedef unsigned long long u64;

// ---------------- compile-time GF(2) linear algebra (10x10 bit matrices) ----
struct M10 { unsigned r[10]; };

__host__ __device__ constexpr M10 midentity() {
    M10 m{{0,0,0,0,0,0,0,0,0,0}};
    for (int i = 0; i < 10; i++) m.r[i] = 1u << i;
    return m;
}
__host__ __device__ constexpr M10 mmul(M10 a, M10 b) {
    M10 c{{0,0,0,0,0,0,0,0,0,0}};
    for (int i = 0; i < 10; i++) {
        unsigned v = 0;
        for (int j = 0; j < 10; j++)
            if ((a.r[i] >> j) & 1u) v ^= b.r[j];
        c.r[i] = v;
    }
    return c;
}
__host__ __device__ constexpr M10 mcnot(int c, int t) {
    M10 m = midentity();
    m.r[t] ^= (1u << c);
    return m;
}
__host__ __device__ constexpr M10 rmat() {
    M10 p = mcnot(0, 1);
    for (int c = 1; c < 10; c++) p = mmul(p, mcnot(c, (c + 1) % 10));
    return p;
}
__host__ __device__ constexpr M10 rinvmat() {
    M10 p = mcnot(9, 0);
    for (int c = 8; c >= 0; c--) p = mmul(p, mcnot(c, c + 1));
    return p;
}
// Invariant: stored[p] = true[T_l p],  T_l = (R^-1)^l,  Tinv_l = R^l
__host__ __device__ constexpr M10 tmat(int l) {
    M10 t = midentity();
    for (int k = 0; k < l; k++) t = mmul(rinvmat(), t);
    return t;
}
__host__ __device__ constexpr M10 tinvmat(int l) {
    M10 t = midentity();
    for (int k = 0; k < l; k++) t = mmul(t, rmat());
    return t;
}
__host__ __device__ constexpr unsigned t_row(int l, int q) { return tmat(l).r[q]; }
__host__ __device__ constexpr unsigned tinv_col(int l, int q) {
    M10 ti = tinvmat(l);
    unsigned v = 0;
    for (int i = 0; i < 10; i++) v |= ((ti.r[i] >> q) & 1u) << i;
    return v;
}
__host__ __device__ constexpr unsigned parity_(unsigned x) {
    x ^= x >> 16; x ^= x >> 8; x ^= x >> 4; x ^= x >> 2; x ^= x >> 1;
    return x & 1u;
}
// 8-entry parity bitmap over pack index: bit k = parity(k & m)
__host__ __device__ constexpr unsigned blow8(unsigned m) {
    unsigned r = 0;
    for (unsigned k = 0; k < 8; k++) r |= parity_(k & m) << k;
    return r;
}
// warp-bit signs of the measurement rows (bit q = bit9 of row q of T_4)
__host__ __device__ constexpr unsigned wsgn_() {
    unsigned r = 0;
    for (int q = 0; q < 10; q++) r |= ((t_row(4, q) >> 9) & 1u) << q;
    return r;
}
constexpr unsigned WSGN = wsgn_();

// ---------------- weight-derived trig table (batch independent) -------------
__device__ float4 g_wtab[40];   // per gate: (cos w1/2, sin w1/2, cos w0/2, sin w0/2)

__global__ void prep_kernel(const float* __restrict__ w) {
    int g = threadIdx.x;
    if (g < 40) {
        float w0 = w[2 * g + 0];
        float w1 = w[2 * g + 1];
        float4 t;
        t.x = cosf(0.5f * w1);
        t.y = sinf(0.5f * w1);
        t.z = cosf(0.5f * w0);
        t.w = sinf(0.5f * w0);
        g_wtab[g] = t;
    }
}

// ---------------- packed f32x2 primitives ------------------------------------
__device__ __forceinline__ u64 pack2(float lo, float hi) {
    u64 r;
    asm("mov.b64 %0, {%1, %2};" : "=l"(r) : "f"(lo), "f"(hi));
    return r;
}
__device__ __forceinline__ void unpack2(u64 v, float& lo, float& hi) {
    asm("mov.b64 {%0, %1}, %2;" : "=f"(lo), "=f"(hi) : "l"(v));
}
__device__ __forceinline__ u64 swp(u64 v) {
    float lo, hi;
    unpack2(v, lo, hi);
    return pack2(hi, lo);
}
__device__ __forceinline__ u64 fma2(u64 a, u64 b, u64 c) {
    u64 d;
    asm("fma.rn.f32x2 %0, %1, %2, %3;" : "=l"(d) : "l"(a), "l"(b), "l"(c));
    return d;
}
__device__ __forceinline__ u64 mul2(u64 a, u64 b) {
    u64 d;
    asm("mul.rn.f32x2 %0, %1, %2;" : "=l"(d) : "l"(a), "l"(b));
    return d;
}
__device__ __forceinline__ u64 add2(u64 a, u64 b) {
    u64 d;
    asm("add.rn.f32x2 %0, %1, %2;" : "=l"(d) : "l"(a), "l"(b));
    return d;
}
__device__ __forceinline__ u64 shx64(u64 v, int m) {
    return __shfl_xor_sync(FULLM, v, m);
}
__device__ __forceinline__ void barsync(int bid) {
    asm volatile("bar.sync %0, 64;" :: "r"(bid) : "memory");
}

// element update, side bit t (compile-time after unroll):
//   RE' = alx*REa - tau*aly*IMa - tau*bex*REb - bey*IMb
//   IM' = alx*IMa + tau*aly*REa - tau*bex*IMb + bey*REb
#define UPD(t, REa, IMa, REb, IMb, REo, IMo) do {                               \
    u64 _tay  = (t) ? TAY1 : TAY0;                                              \
    u64 _ntay = (t) ? TAY0 : TAY1;                                              \
    u64 _ntbx = (t) ? TBX0 : TBX1;                                              \
    u64 _ro = fma2(ALX, (REa), fma2(_ntay, (IMa), fma2(_ntbx, (REb), mul2(NBEY, (IMb))))); \
    u64 _io = fma2(ALX, (IMa), fma2(_tay,  (REa), fma2(_ntbx, (IMb), mul2(BEY,  (REb))))); \
    (REo) = _ro; (IMo) = _io; } while (0)

// ---------------- one gate (fully unrolled, masks are immediates) ------------
template <int G>
__device__ __forceinline__ void apply_gate(u64 (&RE)[8], u64 (&IM)[8],
                                           int lane, int w, int bid,
                                           u64* __restrict__ xb_my,
                                           const u64* __restrict__ xb_ot,
                                           float2 A0, float2 B0,
                                           float2 A1, float2 B1) {
    constexpr unsigned rm = t_row(G / 10, G % 10);
    constexpr unsigned v  = tinv_col(G / 10, G % 10);
    constexpr unsigned vp = v & 7u, vs = (v >> 3) & 1u;
    constexpr unsigned vl = (v >> 4) & 31u, vw = (v >> 9) & 1u;
    constexpr unsigned rp = rm & 7u, rs = (rm >> 3) & 1u;
    constexpr unsigned rl = (rm >> 4) & 31u, rw = (rm >> 9) & 1u;
    constexpr unsigned PARK = blow8(rp);
    constexpr int src = G & 31;

    // broadcast alpha, beta (computed by owner lane; identical in both warps)
    float alx = __shfl_sync(FULLM, (G < 32) ? A0.x : A1.x, src);
    float aly = __shfl_sync(FULLM, (G < 32) ? A0.y : A1.y, src);
    float bex = __shfl_sync(FULLM, (G < 32) ? B0.x : B1.x, src);
    float bey = __shfl_sync(FULLM, (G < 32) ? B0.y : B1.y, src);

    bool blane = ((__popc(lane & (int)rl) ^ (w & (int)rw)) & 1) != 0;
    float e  = blane ? -1.f : 1.f;
    float ey = e * aly, ex = e * bex;
    float sy = rs ? -ey : ey;      // hi-slot sign factor
    float sx = rs ? -ex : ex;

    u64 ALX  = pack2(alx, alx);
    u64 BEY  = pack2(bey, bey);
    u64 NBEY = pack2(-bey, -bey);
    u64 TAY0 = pack2(ey, sy),  TAY1 = pack2(-ey, -sy);
    u64 TBX0 = pack2(ex, sx),  TBX1 = pack2(-ex, -sx);

    if (vw) {
        // cross-warp: snapshot exchange through shared memory
        #pragma unroll
        for (int k = 0; k < 8; k++) {
            xb_my[k * 32 + lane]       = RE[k];
            xb_my[(k + 8) * 32 + lane] = IM[k];
        }
        barsync(bid);
        const int pl = lane ^ (int)vl;
        #pragma unroll
        for (int k = 0; k < 8; k++) {
            u64 pr = xb_ot[(k ^ (int)vp) * 32 + pl];
            u64 pi = xb_ot[((k ^ (int)vp) + 8) * 32 + pl];
            if (vs) { pr = swp(pr); pi = swp(pi); }
            UPD((PARK >> k) & 1u, RE[k], IM[k], pr, pi, RE[k], IM[k]);
        }
        barsync(bid);
    } else if (vl) {
        if (vp == 0u) {
            #pragma unroll
            for (int k = 0; k < 8; k++) {
                u64 pr = shx64(RE[k], (int)vl);
                u64 pi = shx64(IM[k], (int)vl);
                if (vs) { pr = swp(pr); pi = swp(pi); }
                UPD((PARK >> k) & 1u, RE[k], IM[k], pr, pi, RE[k], IM[k]);
            }
        } else {
            // pair-lockstep: all shuffles of a pair read pre-update values
            constexpr unsigned hb = vp & (0u - vp);
            #pragma unroll
            for (int k = 0; k < 8; k++) {
                if ((k & (int)hb) == 0) {
                    const int kb = k ^ (int)vp;
                    u64 pAr = shx64(RE[kb], (int)vl);
                    u64 pAi = shx64(IM[kb], (int)vl);
                    u64 pBr = shx64(RE[k],  (int)vl);
                    u64 pBi = shx64(IM[k],  (int)vl);
                    if (vs) { pAr = swp(pAr); pAi = swp(pAi);
                              pBr = swp(pBr); pBi = swp(pBi); }
                    u64 ra = RE[k], ia = IM[k], rb = RE[kb], ib = IM[kb];
                    UPD((PARK >> k)  & 1u, ra, ia, pAr, pAi, RE[k],  IM[k]);
                    UPD((PARK >> kb) & 1u, rb, ib, pBr, pBi, RE[kb], IM[kb]);
                }
            }
        }
    } else {
        if (vp == 0u) {
            // vs==1: partner is the other slot of the same pack
            #pragma unroll
            for (int k = 0; k < 8; k++) {
                u64 rb = swp(RE[k]), ib = swp(IM[k]);
                UPD((PARK >> k) & 1u, RE[k], IM[k], rb, ib, RE[k], IM[k]);
            }
        } else {
            constexpr unsigned hb = vp & (0u - vp);
            #pragma unroll
            for (int k = 0; k < 8; k++) {
                if ((k & (int)hb) == 0) {
                    const int kb = k ^ (int)vp;
                    u64 ra = RE[k],  ia = IM[k];
                    u64 rb = RE[kb], ib = IM[kb];
                    u64 rbS = vs ? swp(rb) : rb, ibS = vs ? swp(ib) : ib;
                    u64 raS = vs ? swp(ra) : ra, iaS = vs ? swp(ia) : ia;
                    UPD((PARK >> k)  & 1u, ra, ia, rbS, ibS, RE[k],  IM[k]);
                    UPD((PARK >> kb) & 1u, rb, ib, raS, iaS, RE[kb], IM[kb]);
                }
            }
        }
    }
}

template <int G>
struct GLoop {
    static __device__ __forceinline__ void run(u64 (&RE)[8], u64 (&IM)[8],
                                               int lane, int w, int bid,
                                               u64* xb_my, const u64* xb_ot,
                                               float2 A0, float2 B0,
                                               float2 A1, float2 B1) {
        apply_gate<G>(RE, IM, lane, w, bid, xb_my, xb_ot, A0, B0, A1, B1);
        GLoop<G + 1>::run(RE, IM, lane, w, bid, xb_my, xb_ot, A0, B0, A1, B1);
    }
};
template <>
struct GLoop<40> {
    static __device__ __forceinline__ void run(u64 (&)[8], u64 (&)[8], int, int, int,
                                               u64*, const u64*,
                                               float2, float2, float2, float2) {}
};

// ---------------- measurement: <Z_q> with final transform T_4 ----------------
template <int Q>
__device__ __forceinline__ float zsum8(const u64 (&pr2)[8], int lane) {
    constexpr unsigned fm = t_row(4, Q);
    constexpr unsigned fp = fm & 7u, fs = (fm >> 3) & 1u, fl = (fm >> 4) & 31u;
    constexpr unsigned PARK = blow8(fp);
    const u64 SGNp = pack2(1.f,  fs ? -1.f :  1.f);
    const u64 SGNm = pack2(-1.f, fs ?  1.f : -1.f);
    u64 acc0 = 0ull, acc1 = 0ull;
    #pragma unroll
    for (int k = 0; k < 4; k++)
        acc0 = fma2(pr2[k], ((PARK >> k) & 1u) ? SGNm : SGNp, acc0);
    #pragma unroll
    for (int k = 4; k < 8; k++)
        acc1 = fma2(pr2[k], ((PARK >> k) & 1u) ? SGNm : SGNp, acc1);
    float lo, hi;
    unpack2(add2(acc0, acc1), lo, hi);
    float s = lo + hi;
    if (__popc(lane & (int)fl) & 1) s = -s;
    return s;    // warp-bit sign applied at the cross-warp combine
}

template <int Q>   // processes Q and Q+1 together (Q even); lane0 stores pair
struct M2 {
    static __device__ __forceinline__ void run(const u64 (&pr2)[8], int lane,
                                               u64* __restrict__ msm) {
        float sA = zsum8<Q>(pr2, lane);
        float sB = zsum8<Q + 1>(pr2, lane);
        u64 vv = pack2(sA, sB);
        #pragma unroll
        for (int off = 16; off; off >>= 1)
            vv = add2(vv, shx64(vv, off));
        if (lane == 0) msm[Q / 2] = vv;
        M2<Q + 2>::run(pr2, lane, msm);
    }
};
template <>
struct M2<10> {
    static __device__ __forceinline__ void run(const u64 (&)[8], int, u64*) {}
};

// compute (alpha, beta) for one gate from its angle trig + weight trig
__device__ __forceinline__ void gate_coeffs(float ca, float sa, float4 wt,
                                            float2& al, float2& be) {
    float cw = wt.x, sw = wt.y, cph = wt.z, sph = wt.w;
    float A = cw * ca, B = sw * sa, C = sw * ca, D = cw * sa;
    al = make_float2((A - B) * cph, -(A + B) * sph);
    be = make_float2((C + D) * cph,  (D - C) * sph);
}

// ---------------- main kernel ------------------------------------------------
__global__ void __launch_bounds__(128, 6)
qsim_kernel(const float* __restrict__ x, float* __restrict__ out, int B) {
    __shared__ __align__(16) u64 xbuf[2][2][512];   // [batch][warp][16 rows x 32 lanes]

    const int tid  = threadIdx.x;
    const int lane = tid & 31;
    const int w    = (tid >> 5) & 1;
    const int bi   = tid >> 6;
    const int bglob = blockIdx.x * 2 + bi;
    if (bglob >= B) return;
    const int bid = bi + 1;   // named barrier id per batch group

    u64* xb_my       = &xbuf[bi][w][0];
    const u64* xb_ot = &xbuf[bi][w ^ 1][0];

    const float* xb = x + (size_t)bglob * 40;
    const float PI_F = 3.14159265358979f;

    // ---- per-gate coefficients: lane g owns gate g (set0) and gate 32+g (set1)
    float ca0, sa0;
    __sincosf(0.5f * PI_F * atanf(xb[lane]), &sa0, &ca0);
    float2 A0, B0;
    gate_coeffs(ca0, sa0, g_wtab[lane], A0, B0);

    float2 A1 = make_float2(1.f, 0.f), B1 = make_float2(0.f, 0.f);
    if (lane < 8) {
        float ca1, sa1;
        __sincosf(0.5f * PI_F * atanf(xb[32 + lane]), &sa1, &ca1);
        gate_coeffs(ca1, sa1, g_wtab[32 + lane], A1, B1);
    }

    // ---- layer 0: product state in split layout ----
    // lane factor: qubits 4..8 by lane bits; qubit 9 by warp bit
    float fzr, fzi;
    {
        float ax = __shfl_sync(FULLM, A0.x, 4), ay = __shfl_sync(FULLM, A0.y, 4);
        float bx = __shfl_sync(FULLM, B0.x, 4), by = __shfl_sync(FULLM, B0.y, 4);
        fzr = (lane & 1) ? bx : ax;
        fzi = (lane & 1) ? by : ay;
        #pragma unroll
        for (int j = 1; j < 5; j++) {
            const int sl = 4 + j;
            float cax = __shfl_sync(FULLM, A0.x, sl), cay = __shfl_sync(FULLM, A0.y, sl);
            float cbx = __shfl_sync(FULLM, B0.x, sl), cby = __shfl_sync(FULLM, B0.y, sl);
            float cx = ((lane >> j) & 1) ? cbx : cax;
            float cy = ((lane >> j) & 1) ? cby : cay;
            float nr = fzr * cx - fzi * cy;
            float ni = fzr * cy + fzi * cx;
            fzr = nr; fzi = ni;
        }
        // warp qubit 9
        float a9x = __shfl_sync(FULLM, A0.x, 9), a9y = __shfl_sync(FULLM, A0.y, 9);
        float b9x = __shfl_sync(FULLM, B0.x, 9), b9y = __shfl_sync(FULLM, B0.y, 9);
        float cx = w ? b9x : a9x;
        float cy = w ? b9y : a9y;
        float nr = fzr * cx - fzi * cy;
        float ni = fzr * cy + fzi * cx;
        fzr = nr; fzi = ni;
    }

    u64 RE[8], IM[8];
    // slot qubit = logical 3
    {
        float a3x = __shfl_sync(FULLM, A0.x, 3), a3y = __shfl_sync(FULLM, A0.y, 3);
        float b3x = __shfl_sync(FULLM, B0.x, 3), b3y = __shfl_sync(FULLM, B0.y, 3);
        RE[0] = pack2(fzr * a3x - fzi * a3y, fzr * b3x - fzi * b3y);
        IM[0] = pack2(fzr * a3y + fzi * a3x, fzr * b3y + fzi * b3x);
    }
    // pack-bit doubling over logical qubits 0,1,2
    #pragma unroll
    for (int j = 0; j < 3; j++) {
        float u0x = __shfl_sync(FULLM, A0.x, j), u0y = __shfl_sync(FULLM, A0.y, j);
        float u1x = __shfl_sync(FULLM, B0.x, j), u1y = __shfl_sync(FULLM, B0.y, j);
        u64 U0X = pack2(u0x, u0x), U0Y = pack2(u0y, u0y), NU0Y = pack2(-u0y, -u0y);
        u64 U1X = pack2(u1x, u1x), U1Y = pack2(u1y, u1y), NU1Y = pack2(-u1y, -u1y);
        #pragma unroll
        for (int k = 0; k < 8; k++) {
            if (k < (1 << j)) {
                u64 rr = RE[k], ii = IM[k];
                RE[k | (1 << j)] = fma2(U1X, rr, mul2(NU1Y, ii));
                IM[k | (1 << j)] = fma2(U1X, ii, mul2(U1Y,  rr));
                RE[k]            = fma2(U0X, rr, mul2(NU0Y, ii));
                IM[k]            = fma2(U0X, ii, mul2(U0Y,  rr));
            }
        }
    }

    // ---- layers 1..3 (gates 10..39) ----
    GLoop<10>::run(RE, IM, lane, w, bid, xb_my, xb_ot, A0, B0, A1, B1);

    // ---- probabilities (packed) + <Z_q> ----
    u64 pr2[8];
    #pragma unroll
    for (int k = 0; k < 8; k++)
        pr2[k] = fma2(RE[k], RE[k], mul2(IM[k], IM[k]));

    // per-warp partial sums for all 10 observables -> smem
    M2<0>::run(pr2, lane, xb_my);
    barsync(bid);

    // combine the warp pair (warp-bit sign from WSGN) and write out
    if (w == 0 && lane < 5) {
        u64 a = xb_my[lane];   // warp 0 partials (pair 2*lane, 2*lane+1)
        u64 c = xb_ot[lane];   // warp 1 partials
        float s0 = ((WSGN >> (2 * lane))     & 1u) ? -1.f : 1.f;
        float s1 = ((WSGN >> (2 * lane + 1)) & 1u) ? -1.f : 1.f;
        u64 r = fma2(pack2(s0, s1), c, a);
        float* outp = out + (size_t)bglob * 10;
        *reinterpret_cast<u64*>(outp + 2 * lane) = r;   // 8B-aligned
    }
}

// ---------------- launch -----------------------------------------------------
extern "C" void kernel_launch(void* const* d_in, const int* in_sizes, int n_in,
                              void* d_out, int out_size) {
    const float* x = (const float*)d_in[0];   // [B, 40] fp32
    const float* w = (const float*)d_in[1];   // [4, 10, 2] fp32
    float* out = (float*)d_out;               // [B, 10] fp32

    int B = in_sizes[0] / 40;
    prep_kernel<<<1, 64>>>(w);
    int blocks = (B + 1) / 2;                 // 2 batch elements per 128-thread block
    qsim_kernel<<<blocks, 128>>>(x, out, B);
}

// round 14
// speedup vs baseline: 1.0020x; 1.0020x over previous
#include <cuda_runtime.h>
#include <cuda_bf16.h>
#include <cstdint>

// ============================================================================
// ReuploadingQuantumLayer: 10-qubit statevector sim, 4 layers, B=16384.
// TWO warps per batch element (64 lanes): 16 amps/lane = 8 packed f32x2 RE +
// 8 packed IM regs. Physical index bits: [0..2]=pack, [3]=slot, [4..8]=lane,
// [9]=warp. Cross-warp gates (8 of 30) exchange state via shared memory with
// named 64-thread barriers; cross-lane gates (16) use shfl; 6 gates are
// register-local. CNOT rings tracked as compile-time GF(2) basis transform.
// Layer 0 exploits |0..0>: direct product-state construction.
// All arithmetic via Blackwell packed fma.rn.f32x2.
// ============================================================================

#define FULLM 0xFFFFFFFFu
typedef unsigned long long u64;

// ---------------- compile-time GF(2) linear algebra (10x10 bit matrices) ----
struct M10 { unsigned r[10]; };

__host__ __device__ constexpr M10 midentity() {
    M10 m{{0,0,0,0,0,0,0,0,0,0}};
    for (int i = 0; i < 10; i++) m.r[i] = 1u << i;
    return m;
}
__host__ __device__ constexpr M10 mmul(M10 a, M10 b) {
    M10 c{{0,0,0,0,0,0,0,0,0,0}};
    for (int i = 0; i < 10; i++) {
        unsigned v = 0;
        for (int j = 0; j < 10; j++)
            if ((a.r[i] >> j) & 1u) v ^= b.r[j];
        c.r[i] = v;
    }
    return c;
}
__host__ __device__ constexpr M10 mcnot(int c, int t) {
    M10 m = midentity();
    m.r[t] ^= (1u << c);
    return m;
}
__host__ __device__ constexpr M10 rmat() {
    M10 p = mcnot(0, 1);
    for (int c = 1; c < 10; c++) p = mmul(p, mcnot(c, (c + 1) % 10));
    return p;
}
__host__ __device__ constexpr M10 rinvmat() {
    M10 p = mcnot(9, 0);
    for (int c = 8; c >= 0; c--) p = mmul(p, mcnot(c, c + 1));
    return p;
}
// Invariant: stored[p] = true[T_l p],  T_l = (R^-1)^l,  Tinv_l = R^l
__host__ __device__ constexpr M10 tmat(int l) {
    M10 t = midentity();
    for (int k = 0; k < l; k++) t = mmul(rinvmat(), t);
    return t;
}
__host__ __device__ constexpr M10 tinvmat(int l) {
    M10 t = midentity();
    for (int k = 0; k < l; k++) t = mmul(t, rmat());
    return t;
}
__host__ __device__ constexpr unsigned t_row(int l, int q) { return tmat(l).r[q]; }
__host__ __device__ constexpr unsigned tinv_col(int l, int q) {
    M10 ti = tinvmat(l);
    unsigned v = 0;
    for (int i = 0; i < 10; i++) v |= ((ti.r[i] >> q) & 1u) << i;
    return v;
}
__host__ __device__ constexpr unsigned parity_(unsigned x) {
    x ^= x >> 16; x ^= x >> 8; x ^= x >> 4; x ^= x >> 2; x ^= x >> 1;
    return x & 1u;
}
// 8-entry parity bitmap over pack index: bit k = parity(k & m)
__host__ __device__ constexpr unsigned blow8(unsigned m) {
    unsigned r = 0;
    for (unsigned k = 0; k < 8; k++) r |= parity_(k & m) << k;
    return r;
}
// warp-bit signs of the measurement rows (bit q = bit9 of row q of T_4)
__host__ __device__ constexpr unsigned wsgn_() {
    unsigned r = 0;
    for (int q = 0; q < 10; q++) r |= ((t_row(4, q) >> 9) & 1u) << q;
    return r;
}
constexpr unsigned WSGN = wsgn_();

// ---------------- weight-derived trig table (batch independent) -------------
__device__ float4 g_wtab[40];   // per gate: (cos w1/2, sin w1/2, cos w0/2, sin w0/2)

__global__ void prep_kernel(const float* __restrict__ w) {
    int g = threadIdx.x;
    if (g < 40) {
        float w0 = w[2 * g + 0];
        float w1 = w[2 * g + 1];
        float4 t;
        t.x = cosf(0.5f * w1);
        t.y = sinf(0.5f * w1);
        t.z = cosf(0.5f * w0);
        t.w = sinf(0.5f * w0);
        g_wtab[g] = t;
    }
}

// ---------------- packed f32x2 primitives ------------------------------------
__device__ __forceinline__ u64 pack2(float lo, float hi) {
    u64 r;
    asm("mov.b64 %0, {%1, %2};" : "=l"(r) : "f"(lo), "f"(hi));
    return r;
}
__device__ __forceinline__ void unpack2(u64 v, float& lo, float& hi) {
    asm("mov.b64 {%0, %1}, %2;" : "=f"(lo), "=f"(hi) : "l"(v));
}
__device__ __forceinline__ u64 swp(u64 v) {
    float lo, hi;
    unpack2(v, lo, hi);
    return pack2(hi, lo);
}
__device__ __forceinline__ u64 fma2(u64 a, u64 b, u64 c) {
    u64 d;
    asm("fma.rn.f32x2 %0, %1, %2, %3;" : "=l"(d) : "l"(a), "l"(b), "l"(c));
    return d;
}
__device__ __forceinline__ u64 mul2(u64 a, u64 b) {
    u64 d;
    asm("mul.rn.f32x2 %0, %1, %2;" : "=l"(d) : "l"(a), "l"(b));
    return d;
}
__device__ __forceinline__ u64 add2(u64 a, u64 b) {
    u64 d;
    asm("add.rn.f32x2 %0, %1, %2;" : "=l"(d) : "l"(a), "l"(b));
    return d;
}
__device__ __forceinline__ u64 shx64(u64 v, int m) {
    return __shfl_xor_sync(FULLM, v, m);
}
__device__ __forceinline__ void barsync(int bid) {
    asm volatile("bar.sync %0, 64;" :: "r"(bid) : "memory");
}

// element update, side bit t (compile-time after unroll):
//   RE' = alx*REa - tau*aly*IMa - tau*bex*REb - bey*IMb
//   IM' = alx*IMa + tau*aly*REa - tau*bex*IMb + bey*REb
#define UPD(t, REa, IMa, REb, IMb, REo, IMo) do {                               \
    u64 _tay  = (t) ? TAY1 : TAY0;                                              \
    u64 _ntay = (t) ? TAY0 : TAY1;                                              \
    u64 _ntbx = (t) ? TBX0 : TBX1;                                              \
    u64 _ro = fma2(ALX, (REa), fma2(_ntay, (IMa), fma2(_ntbx, (REb), mul2(NBEY, (IMb))))); \
    u64 _io = fma2(ALX, (IMa), fma2(_tay,  (REa), fma2(_ntbx, (IMb), mul2(BEY,  (REb))))); \
    (REo) = _ro; (IMo) = _io; } while (0)

// ---------------- one gate (fully unrolled, masks are immediates) ------------
template <int G>
__device__ __forceinline__ void apply_gate(u64 (&RE)[8], u64 (&IM)[8],
                                           int lane, int w, int bid,
                                           u64* __restrict__ xb_my,
                                           const u64* __restrict__ xb_ot,
                                           float2 A0, float2 B0,
                                           float2 A1, float2 B1) {
    constexpr unsigned rm = t_row(G / 10, G % 10);
    constexpr unsigned v  = tinv_col(G / 10, G % 10);
    constexpr unsigned vp = v & 7u, vs = (v >> 3) & 1u;
    constexpr unsigned vl = (v >> 4) & 31u, vw = (v >> 9) & 1u;
    constexpr unsigned rp = rm & 7u, rs = (rm >> 3) & 1u;
    constexpr unsigned rl = (rm >> 4) & 31u, rw = (rm >> 9) & 1u;
    constexpr unsigned PARK = blow8(rp);
    constexpr int src = G & 31;

    // broadcast alpha, beta (computed by owner lane; identical in both warps)
    float alx = __shfl_sync(FULLM, (G < 32) ? A0.x : A1.x, src);
    float aly = __shfl_sync(FULLM, (G < 32) ? A0.y : A1.y, src);
    float bex = __shfl_sync(FULLM, (G < 32) ? B0.x : B1.x, src);
    float bey = __shfl_sync(FULLM, (G < 32) ? B0.y : B1.y, src);

    bool blane = ((__popc(lane & (int)rl) ^ (w & (int)rw)) & 1) != 0;
    float e  = blane ? -1.f : 1.f;
    float ey = e * aly, ex = e * bex;
    float sy = rs ? -ey : ey;      // hi-slot sign factor
    float sx = rs ? -ex : ex;

    u64 ALX  = pack2(alx, alx);
    u64 BEY  = pack2(bey, bey);
    u64 NBEY = pack2(-bey, -bey);
    u64 TAY0 = pack2(ey, sy),  TAY1 = pack2(-ey, -sy);
    u64 TBX0 = pack2(ex, sx),  TBX1 = pack2(-ex, -sx);

    if (vw) {
        // cross-warp: snapshot exchange through shared memory
        #pragma unroll
        for (int k = 0; k < 8; k++) {
            xb_my[k * 32 + lane]       = RE[k];
            xb_my[(k + 8) * 32 + lane] = IM[k];
        }
        barsync(bid);
        const int pl = lane ^ (int)vl;
        #pragma unroll
        for (int k = 0; k < 8; k++) {
            u64 pr = xb_ot[(k ^ (int)vp) * 32 + pl];
            u64 pi = xb_ot[((k ^ (int)vp) + 8) * 32 + pl];
            if (vs) { pr = swp(pr); pi = swp(pi); }
            UPD((PARK >> k) & 1u, RE[k], IM[k], pr, pi, RE[k], IM[k]);
        }
        barsync(bid);
    } else if (vl) {
        if (vp == 0u) {
            #pragma unroll
            for (int k = 0; k < 8; k++) {
                u64 pr = shx64(RE[k], (int)vl);
                u64 pi = shx64(IM[k], (int)vl);
                if (vs) { pr = swp(pr); pi = swp(pi); }
                UPD((PARK >> k) & 1u, RE[k], IM[k], pr, pi, RE[k], IM[k]);
            }
        } else {
            // pair-lockstep: all shuffles of a pair read pre-update values
            constexpr unsigned hb = vp & (0u - vp);
            #pragma unroll
            for (int k = 0; k < 8; k++) {
                if ((k & (int)hb) == 0) {
                    const int kb = k ^ (int)vp;
                    u64 pAr = shx64(RE[kb], (int)vl);
                    u64 pAi = shx64(IM[kb], (int)vl);
                    u64 pBr = shx64(RE[k],  (int)vl);
                    u64 pBi = shx64(IM[k],  (int)vl);
                    if (vs) { pAr = swp(pAr); pAi = swp(pAi);
                              pBr = swp(pBr); pBi = swp(pBi); }
                    u64 ra = RE[k], ia = IM[k], rb = RE[kb], ib = IM[kb];
                    UPD((PARK >> k)  & 1u, ra, ia, pAr, pAi, RE[k],  IM[k]);
                    UPD((PARK >> kb) & 1u, rb, ib, pBr, pBi, RE[kb], IM[kb]);
                }
            }
        }
    } else {
        if (vp == 0u) {
            // vs==1: partner is the other slot of the same pack
            #pragma unroll
            for (int k = 0; k < 8; k++) {
                u64 rb = swp(RE[k]), ib = swp(IM[k]);
                UPD((PARK >> k) & 1u, RE[k], IM[k], rb, ib, RE[k], IM[k]);
            }
        } else {
            constexpr unsigned hb = vp & (0u - vp);
            #pragma unroll
            for (int k = 0; k < 8; k++) {
                if ((k & (int)hb) == 0) {
                    const int kb = k ^ (int)vp;
                    u64 ra = RE[k],  ia = IM[k];
                    u64 rb = RE[kb], ib = IM[kb];
                    u64 rbS = vs ? swp(rb) : rb, ibS = vs ? swp(ib) : ib;
                    u64 raS = vs ? swp(ra) : ra, iaS = vs ? swp(ia) : ia;
                    UPD((PARK >> k)  & 1u, ra, ia, rbS, ibS, RE[k],  IM[k]);
                    UPD((PARK >> kb) & 1u, rb, ib, raS, iaS, RE[kb], IM[kb]);
                }
            }
        }
    }
}

template <int G>
struct GLoop {
    static __device__ __forceinline__ void run(u64 (&RE)[8], u64 (&IM)[8],
                                               int lane, int w, int bid,
                                               u64* xb_my, const u64* xb_ot,
                                               float2 A0, float2 B0,
                                               float2 A1, float2 B1) {
        apply_gate<G>(RE, IM, lane, w, bid, xb_my, xb_ot, A0, B0, A1, B1);
        GLoop<G + 1>::run(RE, IM, lane, w, bid, xb_my, xb_ot, A0, B0, A1, B1);
    }
};
template <>
struct GLoop<40> {
    static __device__ __forceinline__ void run(u64 (&)[8], u64 (&)[8], int, int, int,
                                               u64*, const u64*,
                                               float2, float2, float2, float2) {}
};

// ---------------- measurement: <Z_q> with final transform T_4 ----------------
template <int Q>
__device__ __forceinline__ float zsum8(const u64 (&pr2)[8], int lane) {
    constexpr unsigned fm = t_row(4, Q);
    constexpr unsigned fp = fm & 7u, fs = (fm >> 3) & 1u, fl = (fm >> 4) & 31u;
    constexpr unsigned PARK = blow8(fp);
    const u64 SGNp = pack2(1.f,  fs ? -1.f :  1.f);
    const u64 SGNm = pack2(-1.f, fs ?  1.f : -1.f);
    u64 acc0 = 0ull, acc1 = 0ull;
    #pragma unroll
    for (int k = 0; k < 4; k++)
        acc0 = fma2(pr2[k], ((PARK >> k) & 1u) ? SGNm : SGNp, acc0);
    #pragma unroll
    for (int k = 4; k < 8; k++)
        acc1 = fma2(pr2[k], ((PARK >> k) & 1u) ? SGNm : SGNp, acc1);
    float lo, hi;
    unpack2(add2(acc0, acc1), lo, hi);
    float s = lo + hi;
    if (__popc(lane & (int)fl) & 1) s = -s;
    return s;    // warp-bit sign applied at the cross-warp combine
}

template <int Q>   // processes Q and Q+1 together (Q even); lane0 stores pair
struct M2 {
    static __device__ __forceinline__ void run(const u64 (&pr2)[8], int lane,
                                               u64* __restrict__ msm) {
        float sA = zsum8<Q>(pr2, lane);
        float sB = zsum8<Q + 1>(pr2, lane);
        u64 vv = pack2(sA, sB);
        #pragma unroll
        for (int off = 16; off; off >>= 1)
            vv = add2(vv, shx64(vv, off));
        if (lane == 0) msm[Q / 2] = vv;
        M2<Q + 2>::run(pr2, lane, msm);
    }
};
template <>
struct M2<10> {
    static __device__ __forceinline__ void run(const u64 (&)[8], int, u64*) {}
};

// compute (alpha, beta) for one gate from its angle trig + weight trig
__device__ __forceinline__ void gate_coeffs(float ca, float sa, float4 wt,
                                            float2& al, float2& be) {
    float cw = wt.x, sw = wt.y, cph = wt.z, sph = wt.w;
    float A = cw * ca, B = sw * sa, C = sw * ca, D = cw * sa;
    al = make_float2((A - B) * cph, -(A + B) * sph);
    be = make_float2((C + D) * cph,  (D - C) * sph);
}

// ---------------- main kernel ------------------------------------------------
__global__ void __launch_bounds__(128, 6)
qsim_kernel(const float* __restrict__ x, float* __restrict__ out, int B) {
    __shared__ __align__(16) u64 xbuf[2][2][512];   // [batch][warp][16 rows x 32 lanes]

    const int tid  = threadIdx.x;
    const int lane = tid & 31;
    const int w    = (tid >> 5) & 1;
    const int bi   = tid >> 6;
    const int bglob = blockIdx.x * 2 + bi;
    if (bglob >= B) return;
    const int bid = bi + 1;   // named barrier id per batch group

    u64* xb_my       = &xbuf[bi][w][0];
    const u64* xb_ot = &xbuf[bi][w ^ 1][0];

    const float* xb = x + (size_t)bglob * 40;
    const float PI_F = 3.14159265358979f;

    // ---- per-gate coefficients: lane g owns gate g (set0) and gate 32+g (set1)
    float ca0, sa0;
    __sincosf(0.5f * PI_F * atanf(xb[lane]), &sa0, &ca0);
    float2 A0, B0;
    gate_coeffs(ca0, sa0, g_wtab[lane], A0, B0);

    float2 A1 = make_float2(1.f, 0.f), B1 = make_float2(0.f, 0.f);
    if (lane < 8) {
        float ca1, sa1;
        __sincosf(0.5f * PI_F * atanf(xb[32 + lane]), &sa1, &ca1);
        gate_coeffs(ca1, sa1, g_wtab[32 + lane], A1, B1);
    }

    // ---- layer 0: product state in split layout ----
    // lane factor: qubits 4..8 by lane bits; qubit 9 by warp bit
    float fzr, fzi;
    {
        float ax = __shfl_sync(FULLM, A0.x, 4), ay = __shfl_sync(FULLM, A0.y, 4);
        float bx = __shfl_sync(FULLM, B0.x, 4), by = __shfl_sync(FULLM, B0.y, 4);
        fzr = (lane & 1) ? bx : ax;
        fzi = (lane & 1) ? by : ay;
        #pragma unroll
        for (int j = 1; j < 5; j++) {
            const int sl = 4 + j;
            float cax = __shfl_sync(FULLM, A0.x, sl), cay = __shfl_sync(FULLM, A0.y, sl);
            float cbx = __shfl_sync(FULLM, B0.x, sl), cby = __shfl_sync(FULLM, B0.y, sl);
            float cx = ((lane >> j) & 1) ? cbx : cax;
            float cy = ((lane >> j) & 1) ? cby : cay;
            float nr = fzr * cx - fzi * cy;
            float ni = fzr * cy + fzi * cx;
            fzr = nr; fzi = ni;
        }
        // warp qubit 9
        float a9x = __shfl_sync(FULLM, A0.x, 9), a9y = __shfl_sync(FULLM, A0.y, 9);
        float b9x = __shfl_sync(FULLM, B0.x, 9), b9y = __shfl_sync(FULLM, B0.y, 9);
        float cx = w ? b9x : a9x;
        float cy = w ? b9y : a9y;
        float nr = fzr * cx - fzi * cy;
        float ni = fzr * cy + fzi * cx;
        fzr = nr; fzi = ni;
    }

    u64 RE[8], IM[8];
    // slot qubit = logical 3
    {
        float a3x = __shfl_sync(FULLM, A0.x, 3), a3y = __shfl_sync(FULLM, A0.y, 3);
        float b3x = __shfl_sync(FULLM, B0.x, 3), b3y = __shfl_sync(FULLM, B0.y, 3);
        RE[0] = pack2(fzr * a3x - fzi * a3y, fzr * b3x - fzi * b3y);
        IM[0] = pack2(fzr * a3y + fzi * a3x, fzr * b3y + fzi * b3x);
    }
    // pack-bit doubling over logical qubits 0,1,2
    #pragma unroll
    for (int j = 0; j < 3; j++) {
        float u0x = __shfl_sync(FULLM, A0.x, j), u0y = __shfl_sync(FULLM, A0.y, j);
        float u1x = __shfl_sync(FULLM, B0.x, j), u1y = __shfl_sync(FULLM, B0.y, j);
        u64 U0X = pack2(u0x, u0x), U0Y = pack2(u0y, u0y), NU0Y = pack2(-u0y, -u0y);
        u64 U1X = pack2(u1x, u1x), U1Y = pack2(u1y, u1y), NU1Y = pack2(-u1y, -u1y);
        #pragma unroll
        for (int k = 0; k < 8; k++) {
            if (k < (1 << j)) {
                u64 rr = RE[k], ii = IM[k];
                RE[k | (1 << j)] = fma2(U1X, rr, mul2(NU1Y, ii));
                IM[k | (1 << j)] = fma2(U1X, ii, mul2(U1Y,  rr));
                RE[k]            = fma2(U0X, rr, mul2(NU0Y, ii));
                IM[k]            = fma2(U0X, ii, mul2(U0Y,  rr));
            }
        }
    }

    // ---- layers 1..3 (gates 10..39) ----
    GLoop<10>::run(RE, IM, lane, w, bid, xb_my, xb_ot, A0, B0, A1, B1);

    // ---- probabilities (packed) + <Z_q> ----
    u64 pr2[8];
    #pragma unroll
    for (int k = 0; k < 8; k++)
        pr2[k] = fma2(RE[k], RE[k], mul2(IM[k], IM[k]));

    // per-warp partial sums for all 10 observables -> smem
    M2<0>::run(pr2, lane, xb_my);
    barsync(bid);

    // combine the warp pair (warp-bit sign from WSGN) and write out
    if (w == 0 && lane < 5) {
        u64 a = xb_my[lane];   // warp 0 partials (pair 2*lane, 2*lane+1)
        u64 c = xb_ot[lane];   // warp 1 partials
        float s0 = ((WSGN >> (2 * lane))     & 1u) ? -1.f : 1.f;
        float s1 = ((WSGN >> (2 * lane + 1)) & 1u) ? -1.f : 1.f;
        u64 r = fma2(pack2(s0, s1), c, a);
        float* outp = out + (size_t)bglob * 10;
        *reinterpret_cast<u64*>(outp + 2 * lane) = r;   // 8B-aligned
    }
}

// ---------------- launch -----------------------------------------------------
extern "C" void kernel_launch(void* const* d_in, const int* in_sizes, int n_in,
                              void* d_out, int out_size) {
    const float* x = (const float*)d_in[0];   // [B, 40] fp32
    const float* w = (const float*)d_in[1];   // [4, 10, 2] fp32
    float* out = (float*)d_out;               // [B, 10] fp32

    int B = in_sizes[0] / 40;
    prep_kernel<<<1, 64>>>(w);
    int blocks = (B + 1) / 2;                 // 2 batch elements per 128-thread block
    qsim_kernel<<<blocks, 128>>>(x, out, B);
}

// round 15
// speedup vs baseline: 1.5685x; 1.5653x over previous
#include <cuda_runtime.h>
#include <cuda_bf16.h>
#include <cstdint>

// ============================================================================
// ReuploadingQuantumLayer: 10-qubit statevector, 4 layers, B=16384.
// R8 layout: one warp/batch; RE[16], IM[16] packed f32x2; pack k holds the two
// slot amplitudes (slot = bit PBIT of low-5 basis bits); bits 5..9 = lane.
// R14: Euler split U = RZ(phi) RY(theta) RZ(lambda). Mainloop gates are REAL
// RY rotations (2-term packed updates). RZ diagonals merge into 3 boundary
// diagonals applied via WHT angle synthesis + __sincosf + packed rotation.
// Final diagonal drops under |amp|^2. CNOT rings = compile-time GF(2) masks.
// ============================================================================

#define FULLM 0xFFFFFFFFu
typedef unsigned long long u64;

// ---------------- compile-time GF(2) linear algebra -------------------------
struct M10 { unsigned r[10]; };

__host__ __device__ constexpr M10 midentity() {
    M10 m{{0,0,0,0,0,0,0,0,0,0}};
    for (int i = 0; i < 10; i++) m.r[i] = 1u << i;
    return m;
}
__host__ __device__ constexpr M10 mmul(M10 a, M10 b) {
    M10 c{{0,0,0,0,0,0,0,0,0,0}};
    for (int i = 0; i < 10; i++) {
        unsigned v = 0;
        for (int j = 0; j < 10; j++)
            if ((a.r[i] >> j) & 1u) v ^= b.r[j];
        c.r[i] = v;
    }
    return c;
}
__host__ __device__ constexpr M10 mcnot(int c, int t) {
    M10 m = midentity();
    m.r[t] ^= (1u << c);
    return m;
}
__host__ __device__ constexpr M10 rmat() {
    M10 p = mcnot(0, 1);
    for (int c = 1; c < 10; c++) p = mmul(p, mcnot(c, (c + 1) % 10));
    return p;
}
__host__ __device__ constexpr M10 rinvmat() {
    M10 p = mcnot(9, 0);
    for (int c = 8; c >= 0; c--) p = mmul(p, mcnot(c, c + 1));
    return p;
}
__host__ __device__ constexpr M10 tmat(int l) {
    M10 t = midentity();
    for (int k = 0; k < l; k++) t = mmul(rinvmat(), t);
    return t;
}
__host__ __device__ constexpr M10 tinvmat(int l) {
    M10 t = midentity();
    for (int k = 0; k < l; k++) t = mmul(t, rmat());
    return t;
}
__host__ __device__ constexpr unsigned t_row(int l, int q) { return tmat(l).r[q]; }
__host__ __device__ constexpr unsigned tinv_col(int l, int q) {
    M10 ti = tinvmat(l);
    unsigned v = 0;
    for (int i = 0; i < 10; i++) v |= ((ti.r[i] >> q) & 1u) << i;
    return v;
}
__host__ __device__ constexpr unsigned parity_(unsigned x) {
    x ^= x >> 16; x ^= x >> 8; x ^= x >> 4; x ^= x >> 2; x ^= x >> 1;
    return x & 1u;
}

// ---- pack-bit selection (as R8) ----
__host__ __device__ constexpr int count_pbit(int p) {
    int c = 0;
    for (int g = 10; g < 40; g++)
        if ((tinv_col(g / 10, g % 10) >> p) & 1u) c++;
    return c;
}
__host__ __device__ constexpr int best_pbit() {
    int bp = 0, bc = 1000;
    for (int p = 0; p < 5; p++) {
        int c = count_pbit(p);
        if (c < bc) { bc = c; bp = p; }
    }
    return bp;
}
constexpr int PBIT = best_pbit();

__host__ __device__ constexpr unsigned compact5(unsigned m, int P) {
    return (m & ((1u << P) - 1u)) | (((m >> (P + 1)) & 31u) << P);
}
__host__ __device__ constexpr unsigned blow16(unsigned rmK) {
    unsigned r = 0;
    for (unsigned k = 0; k < 16; k++) r |= parity_(k & rmK) << k;
    return r;
}

// ---- boundary factor tables ----
// Boundary B applied before RY-layer B: B==1 -> lambda of layer 1 (10 factors)
// B>=2 -> phi of layer B-1 (10) + lambda of layer B (10)
__host__ __device__ constexpr int bnd_nf(int b) { return (b == 1) ? 10 : 20; }
__host__ __device__ constexpr int bnd_gate(int b, int i) {
    return (b == 1) ? (10 + i) : ((i < 10) ? (10 * (b - 1) + i) : (10 * b + (i - 10)));
}
__host__ __device__ constexpr bool bnd_isphi(int b, int i) {
    return (b == 1) ? false : (i < 10);
}

// ---------------- weight table ------------------------------------------------
__device__ float4 g_wtab[40];

__global__ void prep_kernel(const float* __restrict__ w) {
    int g = threadIdx.x;
    if (g < 40) {
        float w0 = w[2 * g + 0];
        float w1 = w[2 * g + 1];
        float4 t;
        t.x = cosf(0.5f * w1);
        t.y = sinf(0.5f * w1);
        t.z = cosf(0.5f * w0);
        t.w = sinf(0.5f * w0);
        g_wtab[g] = t;
    }
}

// ---------------- packed f32x2 primitives ------------------------------------
__device__ __forceinline__ u64 pack2(float lo, float hi) {
    u64 r;
    asm("mov.b64 %0, {%1, %2};" : "=l"(r) : "f"(lo), "f"(hi));
    return r;
}
__device__ __forceinline__ void unpack2(u64 v, float& lo, float& hi) {
    asm("mov.b64 {%0, %1}, %2;" : "=f"(lo), "=f"(hi) : "l"(v));
}
__device__ __forceinline__ u64 swp(u64 v) {
    float lo, hi;
    unpack2(v, lo, hi);
    return pack2(hi, lo);
}
__device__ __forceinline__ u64 fma2(u64 a, u64 b, u64 c) {
    u64 d;
    asm("fma.rn.f32x2 %0, %1, %2, %3;" : "=l"(d) : "l"(a), "l"(b), "l"(c));
    return d;
}
__device__ __forceinline__ u64 mul2(u64 a, u64 b) {
    u64 d;
    asm("mul.rn.f32x2 %0, %1, %2;" : "=l"(d) : "l"(a), "l"(b));
    return d;
}
__device__ __forceinline__ u64 add2(u64 a, u64 b) {
    u64 d;
    asm("add.rn.f32x2 %0, %1, %2;" : "=l"(d) : "l"(a), "l"(b));
    return d;
}
__device__ __forceinline__ u64 shx64(u64 v, int m) {
    return __shfl_xor_sync(FULLM, v, m);
}

// ---------------- boundary diagonal ------------------------------------------
// Accumulate signed half-angles into G[16] grouped by compact pack-mask.
template <int B, int I>
__device__ __forceinline__ void facc(u64 (&G)[16], int lane, float2 H0, float2 H1) {
    if constexpr (I < bnd_nf(B)) {
        constexpr int g = bnd_gate(B, I);
        constexpr bool isphi = bnd_isphi(B, I);
        constexpr unsigned m   = t_row(g / 10, g % 10);
        constexpr unsigned rml = m & 31u, rmh = m >> 5;
        constexpr unsigned rmP = (rml >> PBIT) & 1u;
        constexpr unsigned mK  = compact5(rml, PBIT);
        constexpr int src = g & 31;
        float h = __shfl_sync(FULLM, (g < 32) ? (isphi ? H0.x : H0.y)
                                              : (isphi ? H1.x : H1.y), src);
        // contribution to angle(p): (2b-1)h, b = parity(p & m)
        float hs = (__popc(lane & (int)rmh) & 1) ? h : -h;   // lane-parity sign
        u64 H = pack2(hs, rmP ? -hs : hs);                   // slot sign
        G[mK] = add2(G[mK], H);
        facc<B, I + 1>(G, lane, H0, H1);
    }
}

template <int B>
__device__ __forceinline__ void boundary(u64 (&RE)[16], u64 (&IM)[16], int lane,
                                         float2 H0, float2 H1) {
    u64 G[16];
    #pragma unroll
    for (int i = 0; i < 16; i++) G[i] = 0ull;
    facc<B, 0>(G, lane, H0, H1);
    // 16-point WHT: G[k] <- sum_c (-1)^parity(k&c) G[c]  (pack-parity signs)
    const u64 NEG1 = pack2(-1.f, -1.f);
    #pragma unroll
    for (int bit = 1; bit < 16; bit <<= 1) {
        #pragma unroll
        for (int k = 0; k < 16; k++) {
            if ((k & bit) == 0) {
                u64 a = G[k], b = G[k | bit];
                G[k]       = add2(a, b);
                G[k | bit] = fma2(NEG1, b, a);   // a - b
            }
        }
    }
    // apply e^{i ang}: RE' = cos*RE - sin*IM ; IM' = cos*IM + sin*RE
    #pragma unroll
    for (int k = 0; k < 16; k++) {
        float a0, a1;
        unpack2(G[k], a0, a1);
        float s0, c0, s1, c1;
        __sincosf(a0, &s0, &c0);
        __sincosf(a1, &s1, &c1);
        u64 C = pack2(c0, c1), S = pack2(s0, s1), NS = pack2(-s0, -s1);
        u64 r = RE[k];
        RE[k] = fma2(C, r,     mul2(NS, IM[k]));
        IM[k] = fma2(C, IM[k], mul2(S,  r));
    }
}

// ---------------- real RY gate (2-term packed updates) ------------------------
template <int GT>
__device__ __forceinline__ void apply_ry(u64 (&RE)[16], u64 (&IM)[16], int lane,
                                         float2 CS0, float2 CS1) {
    constexpr unsigned rm   = t_row(GT / 10, GT % 10);
    constexpr unsigned v    = tinv_col(GT / 10, GT % 10);
    constexpr unsigned vlow = v & 31u,  vhigh = v >> 5;
    constexpr unsigned rml  = rm & 31u, rmh   = rm >> 5;
    constexpr unsigned vP   = (vlow >> PBIT) & 1u;
    constexpr unsigned vK   = compact5(vlow, PBIT);
    constexpr unsigned rmP  = (rml >> PBIT) & 1u;
    constexpr unsigned rmK  = compact5(rml, PBIT);
    constexpr unsigned PARK = blow16(rmK);
    constexpr int src = GT & 31;

    float c = __shfl_sync(FULLM, (GT < 32) ? CS0.x : CS1.x, src);
    float s = __shfl_sync(FULLM, (GT < 32) ? CS0.y : CS1.y, src);
    // partner sign: side t gets (t ? +s : -s), t = blane ^ park(k) ^ slot*rmP
    bool blane = (__popc(lane & (int)rmh) & 1) != 0;
    float se = blane ? s : -s;
    u64 C   = pack2(c, c);
    u64 SE0 = pack2(se,  rmP ? -se :  se);   // park(k)==0
    u64 SE1 = pack2(-se, rmP ?  se : -se);   // park(k)==1

    if (vhigh == 0u) {
        if (vK == 0u) {
            // partner = other slot of same pack
            #pragma unroll
            for (int k = 0; k < 16; k++) {
                u64 S = ((PARK >> k) & 1u) ? SE1 : SE0;
                u64 rb = swp(RE[k]), ib = swp(IM[k]);
                RE[k] = fma2(C, RE[k], mul2(S, rb));
                IM[k] = fma2(C, IM[k], mul2(S, ib));
            }
        } else {
            constexpr unsigned hb = vK & (0u - vK);
            #pragma unroll
            for (int k = 0; k < 16; k++) {
                if ((k & (int)hb) == 0) {
                    const int kb = k ^ (int)vK;
                    u64 Sk = ((PARK >> k)  & 1u) ? SE1 : SE0;
                    u64 Sb = ((PARK >> kb) & 1u) ? SE1 : SE0;
                    u64 ra = RE[k], ia = IM[k];
                    u64 rpk = vP ? swp(RE[kb]) : RE[kb];
                    u64 ipk = vP ? swp(IM[kb]) : IM[kb];
                    u64 rpb = vP ? swp(ra) : ra;
                    u64 ipb = vP ? swp(ia) : ia;
                    RE[k]  = fma2(C, ra,     mul2(Sk, rpk));
                    IM[k]  = fma2(C, ia,     mul2(Sk, ipk));
                    RE[kb] = fma2(C, RE[kb], mul2(Sb, rpb));
                    IM[kb] = fma2(C, IM[kb], mul2(Sb, ipb));
                }
            }
        }
    } else {
        if (vK == 0u) {
            #pragma unroll
            for (int k = 0; k < 16; k++) {
                u64 pr = shx64(RE[k], (int)vhigh);
                u64 pi = shx64(IM[k], (int)vhigh);
                if (vP) { pr = swp(pr); pi = swp(pi); }
                u64 S = ((PARK >> k) & 1u) ? SE1 : SE0;
                RE[k] = fma2(C, RE[k], mul2(S, pr));
                IM[k] = fma2(C, IM[k], mul2(S, pi));
            }
        } else {
            // pair-lockstep: shuffles read pre-update values
            constexpr unsigned hb = vK & (0u - vK);
            #pragma unroll
            for (int k = 0; k < 16; k++) {
                if ((k & (int)hb) == 0) {
                    const int kb = k ^ (int)vK;
                    u64 pAr = shx64(RE[kb], (int)vhigh);
                    u64 pAi = shx64(IM[kb], (int)vhigh);
                    u64 pBr = shx64(RE[k],  (int)vhigh);
                    u64 pBi = shx64(IM[k],  (int)vhigh);
                    if (vP) { pAr = swp(pAr); pAi = swp(pAi);
                              pBr = swp(pBr); pBi = swp(pBi); }
                    u64 Sk = ((PARK >> k)  & 1u) ? SE1 : SE0;
                    u64 Sb = ((PARK >> kb) & 1u) ? SE1 : SE0;
                    RE[k]  = fma2(C, RE[k],  mul2(Sk, pAr));
                    IM[k]  = fma2(C, IM[k],  mul2(Sk, pAi));
                    RE[kb] = fma2(C, RE[kb], mul2(Sb, pBr));
                    IM[kb] = fma2(C, IM[kb], mul2(Sb, pBi));
                }
            }
        }
    }
}

template <int G0, int G1>
__device__ __forceinline__ void ry_run(u64 (&RE)[16], u64 (&IM)[16], int lane,
                                       float2 CS0, float2 CS1) {
    if constexpr (G0 < G1) {
        apply_ry<G0>(RE, IM, lane, CS0, CS1);
        ry_run<G0 + 1, G1>(RE, IM, lane, CS0, CS1);
    }
}

// ---------------- measurement (as R8) -----------------------------------------
template <int Q>
__device__ __forceinline__ float zsum(const u64 (&pr2)[16], int lane) {
    constexpr unsigned fm   = t_row(4, Q);
    constexpr unsigned rml  = fm & 31u, rmh = fm >> 5;
    constexpr unsigned rmP  = (rml >> PBIT) & 1u;
    constexpr unsigned rmK  = compact5(rml, PBIT);
    constexpr unsigned PARK = blow16(rmK);
    const u64 SGNp = pack2(1.f,  rmP ? -1.f :  1.f);
    const u64 SGNm = pack2(-1.f, rmP ?  1.f : -1.f);
    u64 acc0 = 0ull, acc1 = 0ull;
    #pragma unroll
    for (int k = 0; k < 8; k++)
        acc0 = fma2(pr2[k], ((PARK >> k) & 1u) ? SGNm : SGNp, acc0);
    #pragma unroll
    for (int k = 8; k < 16; k++)
        acc1 = fma2(pr2[k], ((PARK >> k) & 1u) ? SGNm : SGNp, acc1);
    float lo, hi;
    unpack2(add2(acc0, acc1), lo, hi);
    float s = lo + hi;
    if (__popc(lane & (int)rmh) & 1) s = -s;
    return s;
}

template <int Q>
struct M2 {
    static __device__ __forceinline__ void run(const u64 (&pr2)[16], int lane,
                                               float* __restrict__ outp) {
        float sA = zsum<Q>(pr2, lane);
        float sB = zsum<Q + 1>(pr2, lane);
        u64 v = pack2(sA, sB);
        #pragma unroll
        for (int off = 16; off; off >>= 1)
            v = add2(v, shx64(v, off));
        if (lane == 0)
            *reinterpret_cast<u64*>(outp + Q) = v;
        M2<Q + 2>::run(pr2, lane, outp);
    }
};
template <>
struct M2<10> {
    static __device__ __forceinline__ void run(const u64 (&)[16], int, float*) {}
};

// (alpha, beta) from angle trig + weight trig
__device__ __forceinline__ void gate_coeffs(float ca, float sa, float4 wt,
                                            float2& al, float2& be) {
    float cw = wt.x, sw = wt.y, cph = wt.z, sph = wt.w;
    float A = cw * ca, B = sw * sa, C = sw * ca, D = cw * sa;
    al = make_float2((A - B) * cph, -(A + B) * sph);
    be = make_float2((C + D) * cph,  (D - C) * sph);
}

// Euler parameters from (alpha, beta): c=|a|, s=|b|, hphi, hlam
__device__ __forceinline__ void euler_params(float2 al, float2 be,
                                             float2& cs, float2& h) {
    float c = sqrtf(al.x * al.x + al.y * al.y);
    float s = sqrtf(be.x * be.x + be.y * be.y);
    float aa = atan2f(al.y, al.x);
    float ab = atan2f(be.y, be.x);
    cs = make_float2(c, s);
    h  = make_float2(0.5f * (ab - aa), -0.5f * (aa + ab));   // (hphi, hlam)
}

// ---------------- main kernel ------------------------------------------------
__global__ void __launch_bounds__(128, 4)
qsim_kernel(const float* __restrict__ x, float* __restrict__ out, int B) {
    const int lane = threadIdx.x & 31;
    const int b = blockIdx.x * (blockDim.x >> 5) + (threadIdx.x >> 5);
    if (b >= B) return;

    const float* xb = x + (size_t)b * 40;
    const float PI_F = 3.14159265358979f;

    // ---- per-gate coefficients ----
    float ca0, sa0;
    __sincosf(0.5f * PI_F * atanf(xb[lane]), &sa0, &ca0);
    float2 A0, B0;
    gate_coeffs(ca0, sa0, g_wtab[lane], A0, B0);

    float2 A1 = make_float2(1.f, 0.f), B1 = make_float2(0.f, 0.f);
    if (lane < 8) {
        float ca1, sa1;
        __sincosf(0.5f * PI_F * atanf(xb[32 + lane]), &sa1, &ca1);
        gate_coeffs(ca1, sa1, g_wtab[32 + lane], A1, B1);
    }

    float2 CS0, H0, CS1, H1;
    euler_params(A0, B0, CS0, H0);
    euler_params(A1, B1, CS1, H1);

    // ---- layer 0: product state (full U), split layout (as R8) ----
    float fzr, fzi;
    {
        float ux = __shfl_sync(FULLM, A0.x, 5), uy = __shfl_sync(FULLM, A0.y, 5);
        float wx = __shfl_sync(FULLM, B0.x, 5), wy = __shfl_sync(FULLM, B0.y, 5);
        fzr = (lane & 1) ? wx : ux;
        fzi = (lane & 1) ? wy : uy;
        #pragma unroll
        for (int j = 1; j < 5; j++) {
            const int srcl = 5 + j;
            float ax = __shfl_sync(FULLM, A0.x, srcl), ay = __shfl_sync(FULLM, A0.y, srcl);
            float bx = __shfl_sync(FULLM, B0.x, srcl), by = __shfl_sync(FULLM, B0.y, srcl);
            float cx = ((lane >> j) & 1) ? bx : ax;
            float cy = ((lane >> j) & 1) ? by : ay;
            float nr = fzr * cx - fzi * cy;
            float ni = fzr * cy + fzi * cx;
            fzr = nr; fzi = ni;
        }
    }

    u64 RE[16], IM[16];
    {
        float ax = __shfl_sync(FULLM, A0.x, PBIT), ay = __shfl_sync(FULLM, A0.y, PBIT);
        float bx = __shfl_sync(FULLM, B0.x, PBIT), by = __shfl_sync(FULLM, B0.y, PBIT);
        RE[0] = pack2(fzr * ax - fzi * ay, fzr * bx - fzi * by);
        IM[0] = pack2(fzr * ay + fzi * ax, fzr * by + fzi * bx);
    }
    #pragma unroll
    for (int j = 0; j < 4; j++) {
        const int q = (j < PBIT) ? j : j + 1;
        float u0x = __shfl_sync(FULLM, A0.x, q), u0y = __shfl_sync(FULLM, A0.y, q);
        float u1x = __shfl_sync(FULLM, B0.x, q), u1y = __shfl_sync(FULLM, B0.y, q);
        u64 U0X = pack2(u0x, u0x), U0Y = pack2(u0y, u0y), NU0Y = pack2(-u0y, -u0y);
        u64 U1X = pack2(u1x, u1x), U1Y = pack2(u1y, u1y), NU1Y = pack2(-u1y, -u1y);
        #pragma unroll
        for (int k = 0; k < 16; k++) {
            if (k < (1 << j)) {
                u64 rr = RE[k], ii = IM[k];
                RE[k | (1 << j)] = fma2(U1X, rr, mul2(NU1Y, ii));
                IM[k | (1 << j)] = fma2(U1X, ii, mul2(U1Y,  rr));
                RE[k]            = fma2(U0X, rr, mul2(NU0Y, ii));
                IM[k]            = fma2(U0X, ii, mul2(U0Y,  rr));
            }
        }
    }

    // ---- layers 1..3: boundary diagonal + real RY sweep ----
    boundary<1>(RE, IM, lane, H0, H1);
    ry_run<10, 20>(RE, IM, lane, CS0, CS1);
    boundary<2>(RE, IM, lane, H0, H1);
    ry_run<20, 30>(RE, IM, lane, CS0, CS1);
    boundary<3>(RE, IM, lane, H0, H1);
    ry_run<30, 40>(RE, IM, lane, CS0, CS1);
    // final phi diagonal dropped: |amp|^2 invariant

    // ---- probabilities + <Z_q> ----
    u64 pr2[16];
    #pragma unroll
    for (int k = 0; k < 16; k++)
        pr2[k] = fma2(RE[k], RE[k], mul2(IM[k], IM[k]));

    M2<0>::run(pr2, lane, out + (size_t)b * 10);
}

// ---------------- launch -----------------------------------------------------
extern "C" void kernel_launch(void* const* d_in, const int* in_sizes, int n_in,
                              void* d_out, int out_size) {
    const float* x = (const float*)d_in[0];   // [B, 40] fp32
    const float* w = (const float*)d_in[1];   // [4, 10, 2] fp32
    float* out = (float*)d_out;               // [B, 10] fp32

    int B = in_sizes[0] / 40;
    prep_kernel<<<1, 64>>>(w);
    const int THREADS = 128;
    int wpb = THREADS / 32;
    int blocks = (B + wpb - 1) / wpb;
    qsim_kernel<<<blocks, THREADS>>>(x, out, B);
}

// round 17
// speedup vs baseline: 1.7732x; 1.1305x over previous
#include <cuda_runtime.h>
#include <cuda_bf16.h>
#include <cstdint>

// ============================================================================
// ReuploadingQuantumLayer: 10-qubit statevector, 4 layers, B=16384.
// R8 layout: one warp/batch; RE[16], IM[16] packed f32x2; pack k holds the two
// slot amplitudes (slot = bit PBIT of low-5 basis bits); bits 5..9 = lane.
// R14: Euler split U = RZ(phi) RY(theta) RZ(lambda); RZ diagonals merged into
// 3 boundary diagonals (WHT angle synthesis + __sincosf + packed rotation).
// R15: RY gates via scaled-Givens (tan) form: out = c*(a +- t*b), t=s/c.
// One fma2 per component per gate; the warp-uniform c factors accumulate into
// a per-layer scalar, restored by one packed scale pass per layer.
// (R16 = R15 resubmitted unchanged: previous bench was an infra failure.)
// ============================================================================

#define FULLM 0xFFFFFFFFu
typedef unsigned long long u64;

// ---------------- compile-time GF(2) linear algebra -------------------------
struct M10 { unsigned r[10]; };

__host__ __device__ constexpr M10 midentity() {
    M10 m{{0,0,0,0,0,0,0,0,0,0}};
    for (int i = 0; i < 10; i++) m.r[i] = 1u << i;
    return m;
}
__host__ __device__ constexpr M10 mmul(M10 a, M10 b) {
    M10 c{{0,0,0,0,0,0,0,0,0,0}};
    for (int i = 0; i < 10; i++) {
        unsigned v = 0;
        for (int j = 0; j < 10; j++)
            if ((a.r[i] >> j) & 1u) v ^= b.r[j];
        c.r[i] = v;
    }
    return c;
}
__host__ __device__ constexpr M10 mcnot(int c, int t) {
    M10 m = midentity();
    m.r[t] ^= (1u << c);
    return m;
}
__host__ __device__ constexpr M10 rmat() {
    M10 p = mcnot(0, 1);
    for (int c = 1; c < 10; c++) p = mmul(p, mcnot(c, (c + 1) % 10));
    return p;
}
__host__ __device__ constexpr M10 rinvmat() {
    M10 p = mcnot(9, 0);
    for (int c = 8; c >= 0; c--) p = mmul(p, mcnot(c, c + 1));
    return p;
}
__host__ __device__ constexpr M10 tmat(int l) {
    M10 t = midentity();
    for (int k = 0; k < l; k++) t = mmul(rinvmat(), t);
    return t;
}
__host__ __device__ constexpr M10 tinvmat(int l) {
    M10 t = midentity();
    for (int k = 0; k < l; k++) t = mmul(t, rmat());
    return t;
}
__host__ __device__ constexpr unsigned t_row(int l, int q) { return tmat(l).r[q]; }
__host__ __device__ constexpr unsigned tinv_col(int l, int q) {
    M10 ti = tinvmat(l);
    unsigned v = 0;
    for (int i = 0; i < 10; i++) v |= ((ti.r[i] >> q) & 1u) << i;
    return v;
}
__host__ __device__ constexpr unsigned parity_(unsigned x) {
    x ^= x >> 16; x ^= x >> 8; x ^= x >> 4; x ^= x >> 2; x ^= x >> 1;
    return x & 1u;
}

// ---- pack-bit selection (as R8) ----
__host__ __device__ constexpr int count_pbit(int p) {
    int c = 0;
    for (int g = 10; g < 40; g++)
        if ((tinv_col(g / 10, g % 10) >> p) & 1u) c++;
    return c;
}
__host__ __device__ constexpr int best_pbit() {
    int bp = 0, bc = 1000;
    for (int p = 0; p < 5; p++) {
        int c = count_pbit(p);
        if (c < bc) { bc = c; bp = p; }
    }
    return bp;
}
constexpr int PBIT = best_pbit();

__host__ __device__ constexpr unsigned compact5(unsigned m, int P) {
    return (m & ((1u << P) - 1u)) | (((m >> (P + 1)) & 31u) << P);
}
__host__ __device__ constexpr unsigned blow16(unsigned rmK) {
    unsigned r = 0;
    for (unsigned k = 0; k < 16; k++) r |= parity_(k & rmK) << k;
    return r;
}

// ---- boundary factor tables ----
__host__ __device__ constexpr int bnd_nf(int b) { return (b == 1) ? 10 : 20; }
__host__ __device__ constexpr int bnd_gate(int b, int i) {
    return (b == 1) ? (10 + i) : ((i < 10) ? (10 * (b - 1) + i) : (10 * b + (i - 10)));
}
__host__ __device__ constexpr bool bnd_isphi(int b, int i) {
    return (b == 1) ? false : (i < 10);
}

// ---------------- weight table ------------------------------------------------
__device__ float4 g_wtab[40];

__global__ void prep_kernel(const float* __restrict__ w) {
    int g = threadIdx.x;
    if (g < 40) {
        float w0 = w[2 * g + 0];
        float w1 = w[2 * g + 1];
        float4 t;
        t.x = cosf(0.5f * w1);
        t.y = sinf(0.5f * w1);
        t.z = cosf(0.5f * w0);
        t.w = sinf(0.5f * w0);
        g_wtab[g] = t;
    }
}

// ---------------- packed f32x2 primitives ------------------------------------
__device__ __forceinline__ u64 pack2(float lo, float hi) {
    u64 r;
    asm("mov.b64 %0, {%1, %2};" : "=l"(r) : "f"(lo), "f"(hi));
    return r;
}
__device__ __forceinline__ void unpack2(u64 v, float& lo, float& hi) {
    asm("mov.b64 {%0, %1}, %2;" : "=f"(lo), "=f"(hi) : "l"(v));
}
__device__ __forceinline__ u64 swp(u64 v) {
    float lo, hi;
    unpack2(v, lo, hi);
    return pack2(hi, lo);
}
__device__ __forceinline__ u64 fma2(u64 a, u64 b, u64 c) {
    u64 d;
    asm("fma.rn.f32x2 %0, %1, %2, %3;" : "=l"(d) : "l"(a), "l"(b), "l"(c));
    return d;
}
__device__ __forceinline__ u64 mul2(u64 a, u64 b) {
    u64 d;
    asm("mul.rn.f32x2 %0, %1, %2;" : "=l"(d) : "l"(a), "l"(b));
    return d;
}
__device__ __forceinline__ u64 add2(u64 a, u64 b) {
    u64 d;
    asm("add.rn.f32x2 %0, %1, %2;" : "=l"(d) : "l"(a), "l"(b));
    return d;
}
__device__ __forceinline__ u64 shx64(u64 v, int m) {
    return __shfl_xor_sync(FULLM, v, m);
}

// ---------------- boundary diagonal ------------------------------------------
template <int B, int I>
__device__ __forceinline__ void facc(u64 (&G)[16], int lane, float2 H0, float2 H1) {
    if constexpr (I < bnd_nf(B)) {
        constexpr int g = bnd_gate(B, I);
        constexpr bool isphi = bnd_isphi(B, I);
        constexpr unsigned m   = t_row(g / 10, g % 10);
        constexpr unsigned rml = m & 31u, rmh = m >> 5;
        constexpr unsigned rmP = (rml >> PBIT) & 1u;
        constexpr unsigned mK  = compact5(rml, PBIT);
        constexpr int src = g & 31;
        float h = __shfl_sync(FULLM, (g < 32) ? (isphi ? H0.x : H0.y)
                                              : (isphi ? H1.x : H1.y), src);
        float hs = (__popc(lane & (int)rmh) & 1) ? h : -h;
        u64 H = pack2(hs, rmP ? -hs : hs);
        G[mK] = add2(G[mK], H);
        facc<B, I + 1>(G, lane, H0, H1);
    }
}

template <int B>
__device__ __forceinline__ void boundary(u64 (&RE)[16], u64 (&IM)[16], int lane,
                                         float2 H0, float2 H1) {
    u64 G[16];
    #pragma unroll
    for (int i = 0; i < 16; i++) G[i] = 0ull;
    facc<B, 0>(G, lane, H0, H1);
    const u64 NEG1 = pack2(-1.f, -1.f);
    #pragma unroll
    for (int bit = 1; bit < 16; bit <<= 1) {
        #pragma unroll
        for (int k = 0; k < 16; k++) {
            if ((k & bit) == 0) {
                u64 a = G[k], b = G[k | bit];
                G[k]       = add2(a, b);
                G[k | bit] = fma2(NEG1, b, a);
            }
        }
    }
    #pragma unroll
    for (int k = 0; k < 16; k++) {
        float a0, a1;
        unpack2(G[k], a0, a1);
        float s0, c0, s1, c1;
        __sincosf(a0, &s0, &c0);
        __sincosf(a1, &s1, &c1);
        u64 C = pack2(c0, c1), S = pack2(s0, s1), NS = pack2(-s0, -s1);
        u64 r = RE[k];
        RE[k] = fma2(C, r,     mul2(NS, IM[k]));
        IM[k] = fma2(C, IM[k], mul2(S,  r));
    }
}

// ---------------- real RY gate, scaled-Givens (tan) form ----------------------
// out_side0 = c*(a - t*b), out_side1 = c*(a + t*b); c deferred into scl.
template <int GT>
__device__ __forceinline__ void apply_ry(u64 (&RE)[16], u64 (&IM)[16], int lane,
                                         float2 TC0, float2 TC1, float& scl) {
    constexpr unsigned rm   = t_row(GT / 10, GT % 10);
    constexpr unsigned v    = tinv_col(GT / 10, GT % 10);
    constexpr unsigned vlow = v & 31u,  vhigh = v >> 5;
    constexpr unsigned rml  = rm & 31u, rmh   = rm >> 5;
    constexpr unsigned vP   = (vlow >> PBIT) & 1u;
    constexpr unsigned vK   = compact5(vlow, PBIT);
    constexpr unsigned rmP  = (rml >> PBIT) & 1u;
    constexpr unsigned rmK  = compact5(rml, PBIT);
    constexpr unsigned PARK = blow16(rmK);
    constexpr int src = GT & 31;

    float t = __shfl_sync(FULLM, (GT < 32) ? TC0.x : TC1.x, src);
    float c = __shfl_sync(FULLM, (GT < 32) ? TC0.y : TC1.y, src);
    scl *= c;
    bool blane = (__popc(lane & (int)rmh) & 1) != 0;
    float te = blane ? t : -t;
    u64 TE0 = pack2(te,  rmP ? -te :  te);   // park(k)==0
    u64 TE1 = pack2(-te, rmP ?  te : -te);   // park(k)==1

    if (vhigh == 0u) {
        if (vK == 0u) {
            // partner = other slot of same pack
            #pragma unroll
            for (int k = 0; k < 16; k++) {
                u64 T = ((PARK >> k) & 1u) ? TE1 : TE0;
                u64 rb = swp(RE[k]), ib = swp(IM[k]);
                RE[k] = fma2(T, rb, RE[k]);
                IM[k] = fma2(T, ib, IM[k]);
            }
        } else {
            constexpr unsigned hb = vK & (0u - vK);
            #pragma unroll
            for (int k = 0; k < 16; k++) {
                if ((k & (int)hb) == 0) {
                    const int kb = k ^ (int)vK;
                    u64 Tk = ((PARK >> k)  & 1u) ? TE1 : TE0;
                    u64 Tb = ((PARK >> kb) & 1u) ? TE1 : TE0;
                    u64 ra = RE[k], ia = IM[k];
                    u64 rpk = vP ? swp(RE[kb]) : RE[kb];
                    u64 ipk = vP ? swp(IM[kb]) : IM[kb];
                    u64 rpb = vP ? swp(ra) : ra;
                    u64 ipb = vP ? swp(ia) : ia;
                    RE[k]  = fma2(Tk, rpk, ra);
                    IM[k]  = fma2(Tk, ipk, ia);
                    RE[kb] = fma2(Tb, rpb, RE[kb]);
                    IM[kb] = fma2(Tb, ipb, IM[kb]);
                }
            }
        }
    } else {
        if (vK == 0u) {
            #pragma unroll
            for (int k = 0; k < 16; k++) {
                u64 pr = shx64(RE[k], (int)vhigh);
                u64 pi = shx64(IM[k], (int)vhigh);
                if (vP) { pr = swp(pr); pi = swp(pi); }
                u64 T = ((PARK >> k) & 1u) ? TE1 : TE0;
                RE[k] = fma2(T, pr, RE[k]);
                IM[k] = fma2(T, pi, IM[k]);
            }
        } else {
            // pair-lockstep: shuffles read pre-update values
            constexpr unsigned hb = vK & (0u - vK);
            #pragma unroll
            for (int k = 0; k < 16; k++) {
                if ((k & (int)hb) == 0) {
                    const int kb = k ^ (int)vK;
                    u64 pAr = shx64(RE[kb], (int)vhigh);
                    u64 pAi = shx64(IM[kb], (int)vhigh);
                    u64 pBr = shx64(RE[k],  (int)vhigh);
                    u64 pBi = shx64(IM[k],  (int)vhigh);
                    if (vP) { pAr = swp(pAr); pAi = swp(pAi);
                              pBr = swp(pBr); pBi = swp(pBi); }
                    u64 Tk = ((PARK >> k)  & 1u) ? TE1 : TE0;
                    u64 Tb = ((PARK >> kb) & 1u) ? TE1 : TE0;
                    RE[k]  = fma2(Tk, pAr, RE[k]);
                    IM[k]  = fma2(Tk, pAi, IM[k]);
                    RE[kb] = fma2(Tb, pBr, RE[kb]);
                    IM[kb] = fma2(Tb, pBi, IM[kb]);
                }
            }
        }
    }
}

template <int G0, int G1>
__device__ __forceinline__ void ry_run(u64 (&RE)[16], u64 (&IM)[16], int lane,
                                       float2 TC0, float2 TC1, float& scl) {
    if constexpr (G0 < G1) {
        apply_ry<G0>(RE, IM, lane, TC0, TC1, scl);
        ry_run<G0 + 1, G1>(RE, IM, lane, TC0, TC1, scl);
    }
}

// restore deferred layer scale
__device__ __forceinline__ void scale_state(u64 (&RE)[16], u64 (&IM)[16], float scl) {
    u64 S = pack2(scl, scl);
    #pragma unroll
    for (int k = 0; k < 16; k++) {
        RE[k] = mul2(S, RE[k]);
        IM[k] = mul2(S, IM[k]);
    }
}

// ---------------- measurement (as R8) -----------------------------------------
template <int Q>
__device__ __forceinline__ float zsum(const u64 (&pr2)[16], int lane) {
    constexpr unsigned fm   = t_row(4, Q);
    constexpr unsigned rml  = fm & 31u, rmh = fm >> 5;
    constexpr unsigned rmP  = (rml >> PBIT) & 1u;
    constexpr unsigned rmK  = compact5(rml, PBIT);
    constexpr unsigned PARK = blow16(rmK);
    const u64 SGNp = pack2(1.f,  rmP ? -1.f :  1.f);
    const u64 SGNm = pack2(-1.f, rmP ?  1.f : -1.f);
    u64 acc0 = 0ull, acc1 = 0ull;
    #pragma unroll
    for (int k = 0; k < 8; k++)
        acc0 = fma2(pr2[k], ((PARK >> k) & 1u) ? SGNm : SGNp, acc0);
    #pragma unroll
    for (int k = 8; k < 16; k++)
        acc1 = fma2(pr2[k], ((PARK >> k) & 1u) ? SGNm : SGNp, acc1);
    float lo, hi;
    unpack2(add2(acc0, acc1), lo, hi);
    float s = lo + hi;
    if (__popc(lane & (int)rmh) & 1) s = -s;
    return s;
}

template <int Q>
struct M2 {
    static __device__ __forceinline__ void run(const u64 (&pr2)[16], int lane,
                                               float* __restrict__ outp) {
        float sA = zsum<Q>(pr2, lane);
        float sB = zsum<Q + 1>(pr2, lane);
        u64 v = pack2(sA, sB);
        #pragma unroll
        for (int off = 16; off; off >>= 1)
            v = add2(v, shx64(v, off));
        if (lane == 0)
            *reinterpret_cast<u64*>(outp + Q) = v;
        M2<Q + 2>::run(pr2, lane, outp);
    }
};
template <>
struct M2<10> {
    static __device__ __forceinline__ void run(const u64 (&)[16], int, float*) {}
};

// (alpha, beta) from angle trig + weight trig
__device__ __forceinline__ void gate_coeffs(float ca, float sa, float4 wt,
                                            float2& al, float2& be) {
    float cw = wt.x, sw = wt.y, cph = wt.z, sph = wt.w;
    float A = cw * ca, B = sw * sa, C = sw * ca, D = cw * sa;
    al = make_float2((A - B) * cph, -(A + B) * sph);
    be = make_float2((C + D) * cph,  (D - C) * sph);
}

// Euler parameters: tc = (tan(theta/2), cos_mag), h = (hphi, hlam)
__device__ __forceinline__ void euler_params(float2 al, float2 be,
                                             float2& tc, float2& h) {
    float c = sqrtf(al.x * al.x + al.y * al.y);
    float s = sqrtf(be.x * be.x + be.y * be.y);
    float aa = atan2f(al.y, al.x);
    float ab = atan2f(be.y, be.x);
    tc = make_float2(__fdividef(s, c), c);
    h  = make_float2(0.5f * (ab - aa), -0.5f * (aa + ab));
}

// ---------------- main kernel ------------------------------------------------
__global__ void __launch_bounds__(128, 4)
qsim_kernel(const float* __restrict__ x, float* __restrict__ out, int B) {
    const int lane = threadIdx.x & 31;
    const int b = blockIdx.x * (blockDim.x >> 5) + (threadIdx.x >> 5);
    if (b >= B) return;

    const float* xb = x + (size_t)b * 40;
    const float PI_F = 3.14159265358979f;

    // ---- per-gate coefficients ----
    float ca0, sa0;
    __sincosf(0.5f * PI_F * atanf(xb[lane]), &sa0, &ca0);
    float2 A0, B0;
    gate_coeffs(ca0, sa0, g_wtab[lane], A0, B0);

    float2 A1 = make_float2(1.f, 0.f), B1 = make_float2(0.f, 0.f);
    if (lane < 8) {
        float ca1, sa1;
        __sincosf(0.5f * PI_F * atanf(xb[32 + lane]), &sa1, &ca1);
        gate_coeffs(ca1, sa1, g_wtab[32 + lane], A1, B1);
    }

    float2 TC0, H0, TC1, H1;
    euler_params(A0, B0, TC0, H0);
    euler_params(A1, B1, TC1, H1);

    // ---- layer 0: product state (full U), split layout ----
    float fzr, fzi;
    {
        float ux = __shfl_sync(FULLM, A0.x, 5), uy = __shfl_sync(FULLM, A0.y, 5);
        float wx = __shfl_sync(FULLM, B0.x, 5), wy = __shfl_sync(FULLM, B0.y, 5);
        fzr = (lane & 1) ? wx : ux;
        fzi = (lane & 1) ? wy : uy;
        #pragma unroll
        for (int j = 1; j < 5; j++) {
            const int srcl = 5 + j;
            float ax = __shfl_sync(FULLM, A0.x, srcl), ay = __shfl_sync(FULLM, A0.y, srcl);
            float bx = __shfl_sync(FULLM, B0.x, srcl), by = __shfl_sync(FULLM, B0.y, srcl);
            float cx = ((lane >> j) & 1) ? bx : ax;
            float cy = ((lane >> j) & 1) ? by : ay;
            float nr = fzr * cx - fzi * cy;
            float ni = fzr * cy + fzi * cx;
            fzr = nr; fzi = ni;
        }
    }

    u64 RE[16], IM[16];
    {
        float ax = __shfl_sync(FULLM, A0.x, PBIT), ay = __shfl_sync(FULLM, A0.y, PBIT);
        float bx = __shfl_sync(FULLM, B0.x, PBIT), by = __shfl_sync(FULLM, B0.y, PBIT);
        RE[0] = pack2(fzr * ax - fzi * ay, fzr * bx - fzi * by);
        IM[0] = pack2(fzr * ay + fzi * ax, fzr * by + fzi * bx);
    }
    #pragma unroll
    for (int j = 0; j < 4; j++) {
        const int q = (j < PBIT) ? j : j + 1;
        float u0x = __shfl_sync(FULLM, A0.x, q), u0y = __shfl_sync(FULLM, A0.y, q);
        float u1x = __shfl_sync(FULLM, B0.x, q), u1y = __shfl_sync(FULLM, B0.y, q);
        u64 U0X = pack2(u0x, u0x), U0Y = pack2(u0y, u0y), NU0Y = pack2(-u0y, -u0y);
        u64 U1X = pack2(u1x, u1x), U1Y = pack2(u1y, u1y), NU1Y = pack2(-u1y, -u1y);
        #pragma unroll
        for (int k = 0; k < 16; k++) {
            if (k < (1 << j)) {
                u64 rr = RE[k], ii = IM[k];
                RE[k | (1 << j)] = fma2(U1X, rr, mul2(NU1Y, ii));
                IM[k | (1 << j)] = fma2(U1X, ii, mul2(U1Y,  rr));
                RE[k]            = fma2(U0X, rr, mul2(NU0Y, ii));
                IM[k]            = fma2(U0X, ii, mul2(U0Y,  rr));
            }
        }
    }

    // ---- layers 1..3: boundary diagonal + scaled-Givens RY sweep ----
    float scl;
    boundary<1>(RE, IM, lane, H0, H1);
    scl = 1.f;
    ry_run<10, 20>(RE, IM, lane, TC0, TC1, scl);
    scale_state(RE, IM, scl);
    boundary<2>(RE, IM, lane, H0, H1);
    scl = 1.f;
    ry_run<20, 30>(RE, IM, lane, TC0, TC1, scl);
    scale_state(RE, IM, scl);
    boundary<3>(RE, IM, lane, H0, H1);
    scl = 1.f;
    ry_run<30, 40>(RE, IM, lane, TC0, TC1, scl);
    scale_state(RE, IM, scl);
    // final phi diagonal dropped: |amp|^2 invariant

    // ---- probabilities + <Z_q> ----
    u64 pr2[16];
    #pragma unroll
    for (int k = 0; k < 16; k++)
        pr2[k] = fma2(RE[k], RE[k], mul2(IM[k], IM[k]));

    M2<0>::run(pr2, lane, out + (size_t)b * 10);
}

// ---------------- launch -----------------------------------------------------
extern "C" void kernel_launch(void* const* d_in, const int* in_sizes, int n_in,
                              void* d_out, int out_size) {
    const float* x = (const float*)d_in[0];   // [B, 40] fp32
    const float* w = (const float*)d_in[1];   // [4, 10, 2] fp32
    float* out = (float*)d_out;               // [B, 10] fp32

    int B = in_sizes[0] / 40;
    prep_kernel<<<1, 64>>>(w);
    const int THREADS = 128;
    int wpb = THREADS / 32;
    int blocks = (B + wpb - 1) / wpb;
    qsim_kernel<<<blocks, THREADS>>>(x, out, B);
}